// round 5
// baseline (speedup 1.0000x reference)
#include <cuda_runtime.h>
#include <math.h>
#include <stdint.h>

#define NN 50000
#define EE 800000
#define GG 64
#define CH 512
#define NB ((NN + CH - 1) / CH)   // 98 chunks
// smem: weights [128][132] floats + staged rows [64][128] u64 (dup'd)
#define GEMM_SMEM (128*132*4 + 64*128*8)

// ---------------- scratch (static device globals; no allocation) ----------------
__device__ int   g_cnt[2][NN];
__device__ int   g_row[2][NN+1];
__device__ int   g_cur[2][NN];
__device__ int   g_csr[2][EE];
__device__ float g_inv[2][NN];
__device__ int   g_bsum[2][128];
__device__ int   g_boff[2][128];
__device__ float g_agg[2][6400000];   // per-branch aggregate
__device__ float g_t[2][6400000];     // partial (X@Wr^T + b)
__device__ float g_hb[4][6400000];    // h0_sc, h0_fc, h1_sc, h1_fc
__device__ float g_pool[GG*256];

// ---------------- f32x2 helpers ----------------
__device__ __forceinline__ void ffma2(uint64_t& c, uint64_t a, uint64_t b) {
    asm("fma.rn.f32x2 %0, %1, %2, %0;" : "+l"(c) : "l"(a), "l"(b));
}
__device__ __forceinline__ uint64_t pack2(float lo, float hi) {
    uint64_t r; asm("mov.b64 %0, {%1, %2};" : "=l"(r) : "f"(lo), "f"(hi)); return r;
}
__device__ __forceinline__ uint64_t dup2(float v) {
    uint64_t r; asm("mov.b64 %0, {%1, %1};" : "=l"(r) : "f"(v)); return r;
}
__device__ __forceinline__ void unpack2(uint64_t p, float& lo, float& hi) {
    asm("mov.b64 {%0, %1}, %2;" : "=f"(lo), "=f"(hi) : "l"(p));
}

// ---------------- zero counters + pooled + row sentinel ----------------
__global__ void zero_kernel() {
    int i = blockIdx.x * blockDim.x + threadIdx.x;
    if (i < 2*NN) ((int*)g_cnt)[i] = 0;
    if (i < GG*256) g_pool[i] = 0.f;
    if (i == 0) { g_row[0][NN] = EE; g_row[1][NN] = EE; }
}

// ---------------- degree histogram (both sets) ----------------
__global__ void count_kernel(const int* __restrict__ dst0, const int* __restrict__ dst1) {
    int e = blockIdx.x * blockDim.x + threadIdx.x;
    if (e < EE)            atomicAdd(&g_cnt[0][dst0[e]], 1);
    else if (e < 2 * EE)   atomicAdd(&g_cnt[1][dst1[e - EE]], 1);
}

// ---------------- phase 1: per-chunk sums ----------------
__global__ void block_reduce_kernel() {     // grid = 2*NB, 256 threads
    int set = blockIdx.x / NB, b = blockIdx.x - set * NB;
    int tid = threadIdx.x;
    int n0 = b * CH + tid;
    int s = 0;
    if (n0 < NN) s += g_cnt[set][n0];
    if (n0 + 256 < NN && tid + 256 < CH) s += g_cnt[set][n0 + 256];
    #pragma unroll
    for (int o = 16; o > 0; o >>= 1) s += __shfl_down_sync(0xffffffffu, s, o);
    __shared__ int ws[8];
    if ((tid & 31) == 0) ws[tid >> 5] = s;
    __syncthreads();
    if (tid == 0) {
        int t = 0;
        #pragma unroll
        for (int w = 0; w < 8; w++) t += ws[w];
        g_bsum[set][b] = t;
    }
}

// ---------------- phase 2: scan chunk sums (1 block) ----------------
__global__ void bsum_scan_kernel() {        // 1 block, 256 threads
    __shared__ int s[2][129];
    int set = threadIdx.x >> 7, i = threadIdx.x & 127;
    int v = (i < NB) ? g_bsum[set][i] : 0;
    s[set][i] = v;
    __syncthreads();
    #pragma unroll
    for (int o = 1; o < 128; o <<= 1) {
        int t = (i >= o) ? s[set][i - o] : 0;
        __syncthreads();
        s[set][i] += t;
        __syncthreads();
    }
    g_boff[set][i] = s[set][i] - v;  // exclusive
}

// ---------------- phase 3: per-chunk scan, write row/cur/inv ----------------
__global__ void chunk_scan_kernel() {       // grid = 2*NB, 512 threads
    int set = blockIdx.x / NB, b = blockIdx.x - set * NB;
    int tid = threadIdx.x, lane = tid & 31, wid = tid >> 5;
    __shared__ int wsum[16];
    int n = b * CH + tid;
    int v = (n < NN) ? g_cnt[set][n] : 0;
    int x = v;
    #pragma unroll
    for (int o = 1; o < 32; o <<= 1) { int y = __shfl_up_sync(0xffffffffu, x, o); if (lane >= o) x += y; }
    if (lane == 31) wsum[wid] = x;
    __syncthreads();
    if (wid == 0 && lane < 16) {
        int w = wsum[lane];
        #pragma unroll
        for (int o = 1; o < 16; o <<= 1) { int y = __shfl_up_sync(0x0000ffffu, w, o); if (lane >= o) w += y; }
        wsum[lane] = w;
    }
    __syncthreads();
    int excl = g_boff[set][b] + (wid ? wsum[wid - 1] : 0) + (x - v);
    if (n < NN) {
        g_row[set][n] = excl;
        g_cur[set][n] = excl;
        g_inv[set][n] = 1.0f / (float)(v > 0 ? v : 1);
    }
}

// ---------------- CSR fill (both sets) ----------------
__global__ void fill_kernel(const int* __restrict__ ei0, const int* __restrict__ ei1) {
    int e = blockIdx.x * blockDim.x + threadIdx.x;
    if (e < EE) {
        int d = ei0[EE + e];
        int p = atomicAdd(&g_cur[0][d], 1);
        g_csr[0][p] = ei0[e];
    } else if (e < 2 * EE) {
        int ee = e - EE;
        int d = ei1[EE + ee];
        int p = atomicAdd(&g_cur[1][d], 1);
        g_csr[1][p] = ei1[ee];
    }
}

// ---------------- mean aggregation, BOTH branches: warp per node ----------------
__global__ void agg_pair_kernel(const float* __restrict__ x0, float* __restrict__ out0,
                                const float* __restrict__ x1, float* __restrict__ out1) {
    int gw = (blockIdx.x * blockDim.x + threadIdx.x) >> 5;
    int lane = threadIdx.x & 31;
    if (gw >= 2 * NN) return;
    int set = (gw >= NN) ? 1 : 0;
    int node = gw - set * NN;
    const float* x = set ? x1 : x0;
    float* out = set ? out1 : out0;
    int s = g_row[set][node], e = g_row[set][node + 1];
    float ax = 0.f, ay = 0.f, az = 0.f, aw = 0.f;
    for (int b = s; b < e; b += 32) {
        int m = min(32, e - b);
        int sid = (lane < m) ? g_csr[set][b + lane] : 0;
        for (int j = 0; j < m; j++) {
            int sj = __shfl_sync(0xffffffffu, sid, j);
            const float4 v = *reinterpret_cast<const float4*>(x + (size_t)sj * 128 + lane * 4);
            ax += v.x; ay += v.y; az += v.z; aw += v.w;
        }
    }
    float inv = g_inv[set][node];
    float4 r; r.x = ax*inv; r.y = ay*inv; r.z = az*inv; r.w = aw*inv;
    *reinterpret_cast<float4*>(out + (size_t)node * 128 + lane * 4) = r;
}

// ---------------- single-matrix GEMM core (both branches in one launch) ----------------
// MODE 0 (xr): out = X @ W^T + bias
// MODE 1 (al): out = relu(T + X @ W^T)
template <int MODE>
__global__ __launch_bounds__(512) void gemm_pair_kernel(
    const float* __restrict__ X0, const float* __restrict__ W0,
    const float* __restrict__ aux0, float* __restrict__ out0,
    const float* __restrict__ X1, const float* __restrict__ W1,
    const float* __restrict__ aux1, float* __restrict__ out1)
{
    extern __shared__ char smraw[];
    float* sW = (float*)smraw;                            // [128][132]  sW[k*132+h]=W[h][k]
    uint64_t* sA = (uint64_t*)(smraw + 128 * 132 * 4);    // [64][128]  dup'd row scalars

    int half = gridDim.x >> 1;
    int br = (blockIdx.x >= half) ? 1 : 0;
    int bid = blockIdx.x - br * half;
    const float* X  = br ? X1 : X0;
    const float* W  = br ? W1 : W0;
    const float* aux = br ? aux1 : aux0;   // bias (MODE 0) or T (MODE 1)
    float* out = br ? out1 : out0;

    for (int idx = threadIdx.x; idx < 128 * 128; idx += 512) {
        int h = idx >> 7, k = idx & 127;
        sW[k * 132 + h] = W[idx];
    }
    int lane = threadIdx.x & 31, wid = threadIdx.x >> 5;

    uint64_t b01 = 0, b23 = 0;
    if (MODE == 0) {
        float4 bv = *reinterpret_cast<const float4*>(aux + lane * 4);
        b01 = pack2(bv.x, bv.y); b23 = pack2(bv.z, bv.w);
    }

    for (int base = bid * 64; base < NN; base += half * 64) {
        __syncthreads();
        // stage 4 rows per warp, duplicated into f32x2 pairs
        #pragma unroll
        for (int rr = 0; rr < 4; rr++) {
            int r = 4 * wid + rr;
            int row = base + r;
            if (row < NN) {
                float4 v = *reinterpret_cast<const float4*>(X + (size_t)row * 128 + lane * 4);
                uint64_t* dst = sA + r * 128 + lane * 4;
                dst[0] = dup2(v.x); dst[1] = dup2(v.y);
                dst[2] = dup2(v.z); dst[3] = dup2(v.w);
            }
        }
        __syncthreads();

        int row0 = base + 4 * wid;
        if (row0 >= NN) continue;
        uint64_t c01[4], c23[4];
        #pragma unroll
        for (int r = 0; r < 4; r++) {
            if (MODE == 0) { c01[r] = b01; c23[r] = b23; }
            else {
                int row = row0 + r;
                if (row < NN) {
                    float4 t = *reinterpret_cast<const float4*>(aux + (size_t)row * 128 + lane * 4);
                    c01[r] = pack2(t.x, t.y); c23[r] = pack2(t.z, t.w);
                } else { c01[r] = 0; c23[r] = 0; }
            }
        }
        const uint64_t* a0 = sA + (4 * wid + 0) * 128;
        const uint64_t* a1 = sA + (4 * wid + 1) * 128;
        const uint64_t* a2 = sA + (4 * wid + 2) * 128;
        const uint64_t* a3 = sA + (4 * wid + 3) * 128;
        #pragma unroll 8
        for (int k = 0; k < 128; k++) {
            const uint64_t* wp = reinterpret_cast<const uint64_t*>(sW + k * 132 + lane * 4);
            uint64_t w01 = wp[0], w23 = wp[1];
            ffma2(c01[0], a0[k], w01); ffma2(c23[0], a0[k], w23);
            ffma2(c01[1], a1[k], w01); ffma2(c23[1], a1[k], w23);
            ffma2(c01[2], a2[k], w01); ffma2(c23[2], a2[k], w23);
            ffma2(c01[3], a3[k], w01); ffma2(c23[3], a3[k], w23);
        }
        #pragma unroll
        for (int r = 0; r < 4; r++) {
            int row = row0 + r;
            if (row >= NN) break;
            float4 c;
            unpack2(c01[r], c.x, c.y);
            unpack2(c23[r], c.z, c.w);
            if (MODE == 1) {
                c.x = fmaxf(c.x, 0.f); c.y = fmaxf(c.y, 0.f);
                c.z = fmaxf(c.z, 0.f); c.w = fmaxf(c.w, 0.f);
            }
            *reinterpret_cast<float4*>(out + (size_t)row * 128 + lane * 4) = c;
        }
    }
}

// ---------------- global add pool (both branches) ----------------
__global__ void pool_pair_kernel(const float* __restrict__ hsc, const float* __restrict__ hfc,
                                 const int* __restrict__ batch) {
    int idx = blockIdx.x * blockDim.x + threadIdx.x;
    if (idx >= 2 * NN * 32) return;
    int br = (idx >= NN * 32) ? 1 : 0;
    int li = idx - br * NN * 32;
    int node = li >> 5, c4 = li & 31;
    int g = batch[node];
    const float* h = br ? hfc : hsc;
    const float4 v = *reinterpret_cast<const float4*>(h + (size_t)node * 128 + c4 * 4);
    float* d = g_pool + g * 256 + br * 128 + c4 * 4;
    atomicAdd(d + 0, v.x); atomicAdd(d + 1, v.y);
    atomicAdd(d + 2, v.z); atomicAdd(d + 3, v.w);
}

// ---------------- MLP head + log_softmax, one block per graph ----------------
__global__ void head_kernel(
    const float* __restrict__ W1, const float* __restrict__ b1,
    const float* __restrict__ W2, const float* __restrict__ b2,
    const float* __restrict__ W3, const float* __restrict__ b3,
    float* __restrict__ out)
{
    __shared__ float sp[256], sh1[128], sh2[64];
    int g = blockIdx.x, t = threadIdx.x;
    sp[t]       = g_pool[g * 256 + t];
    sp[t + 128] = g_pool[g * 256 + 128 + t];
    __syncthreads();
    float a = b1[t];
    const float* w = W1 + t * 256;
    for (int k = 0; k < 256; k++) a += sp[k] * w[k];
    sh1[t] = fmaxf(a, 0.f);
    __syncthreads();
    if (t < 64) {
        float a2 = b2[t];
        const float* w2 = W2 + t * 128;
        for (int k = 0; k < 128; k++) a2 += sh1[k] * w2[k];
        sh2[t] = fmaxf(a2, 0.f);
    }
    __syncthreads();
    if (t == 0) {
        float l0 = b3[0], l1 = b3[1];
        for (int k = 0; k < 64; k++) { l0 += sh2[k] * W3[k]; l1 += sh2[k] * W3[64 + k]; }
        float m = fmaxf(l0, l1);
        float lse = m + logf(expf(l0 - m) + expf(l1 - m));
        out[g * 2 + 0] = l0 - lse;
        out[g * 2 + 1] = l1 - lse;
    }
}

// ---------------- launch ----------------
extern "C" void kernel_launch(void* const* d_in, const int* in_sizes, int n_in,
                              void* d_out, int out_size) {
    const float* sc_x  = (const float*)d_in[0];
    const float* fc_x  = (const float*)d_in[1];
    const int*   sc_ei = (const int*)d_in[2];
    const int*   fc_ei = (const int*)d_in[3];
    const int*   batch = (const int*)d_in[4];
    const float* scWl1 = (const float*)d_in[5];
    const float* scWr1 = (const float*)d_in[6];
    const float* scb1  = (const float*)d_in[7];
    const float* scWl2 = (const float*)d_in[8];
    const float* scWr2 = (const float*)d_in[9];
    const float* scb2  = (const float*)d_in[10];
    const float* fcWl1 = (const float*)d_in[11];
    const float* fcWr1 = (const float*)d_in[12];
    const float* fcb1  = (const float*)d_in[13];
    const float* fcWl2 = (const float*)d_in[14];
    const float* fcWr2 = (const float*)d_in[15];
    const float* fcb2  = (const float*)d_in[16];
    const float* W1    = (const float*)d_in[17];
    const float* bh1   = (const float*)d_in[18];
    const float* W2    = (const float*)d_in[19];
    const float* bh2   = (const float*)d_in[20];
    const float* W3    = (const float*)d_in[21];
    const float* bh3   = (const float*)d_in[22];
    float* out = (float*)d_out;

    cudaFuncSetAttribute(gemm_pair_kernel<0>, cudaFuncAttributeMaxDynamicSharedMemorySize, GEMM_SMEM);
    cudaFuncSetAttribute(gemm_pair_kernel<1>, cudaFuncAttributeMaxDynamicSharedMemorySize, GEMM_SMEM);

    float *aggb, *tb, *hb;
    cudaGetSymbolAddress((void**)&aggb, g_agg);
    cudaGetSymbolAddress((void**)&tb,   g_t);
    cudaGetSymbolAddress((void**)&hb,   g_hb);
    float* agg0 = aggb;
    float* agg1 = aggb + (size_t)6400000;
    float* t0 = tb;
    float* t1 = tb + (size_t)6400000;
    float* h0sc = hb;
    float* h0fc = hb + (size_t)6400000;
    float* h1sc = hb + (size_t)2 * 6400000;
    float* h1fc = hb + (size_t)3 * 6400000;

    int eb2 = (2 * EE + 255) / 256;
    int ab2 = (2 * NN * 32 + 255) / 256;

    zero_kernel<<<(2*NN + 255) / 256, 256>>>();                  // 1
    count_kernel<<<eb2, 256>>>(sc_ei + EE, fc_ei + EE);          // 2
    block_reduce_kernel<<<2 * NB, 256>>>();                      // 3
    // launch #4 -> profiled: layer-1 Wr GEMM (no CSR dependency)
    gemm_pair_kernel<0><<<296, 512, GEMM_SMEM>>>(                // 4
        sc_x, scWr1, scb1, t0,
        fc_x, fcWr1, fcb1, t1);
    bsum_scan_kernel<<<1, 256>>>();                              // 5
    chunk_scan_kernel<<<2 * NB, CH>>>();                         // 6
    fill_kernel<<<eb2, 256>>>(sc_ei, fc_ei);                     // 7

    // layer 1: aggregate + Wl GEMM (adds to t, relu)
    agg_pair_kernel<<<ab2, 256>>>(sc_x, agg0, fc_x, agg1);       // 8
    gemm_pair_kernel<1><<<296, 512, GEMM_SMEM>>>(                // 9
        agg0, scWl1, t0, h0sc,
        agg1, fcWl1, t1, h0fc);

    // layer 2
    gemm_pair_kernel<0><<<296, 512, GEMM_SMEM>>>(                // 10
        h0sc, scWr2, scb2, t0,
        h0fc, fcWr2, fcb2, t1);
    agg_pair_kernel<<<ab2, 256>>>(h0sc, agg0, h0fc, agg1);       // 11
    gemm_pair_kernel<1><<<296, 512, GEMM_SMEM>>>(                // 12
        agg0, scWl2, t0, h1sc,
        agg1, fcWl2, t1, h1fc);

    pool_pair_kernel<<<ab2, 256>>>(h1sc, h1fc, batch);           // 13
    head_kernel<<<GG, 128>>>(W1, bh1, W2, bh2, W3, bh3, out);    // 14
}

// round 6
// speedup vs baseline: 1.2208x; 1.2208x over previous
#include <cuda_runtime.h>
#include <math.h>
#include <stdint.h>

#define NN 50000
#define EE 800000
#define GG 64
#define CH 512
#define NB ((NN + CH - 1) / CH)   // 98 chunks
// smem: 2 weight mats [128][132] f32 + staged rows [64][130] u64
#define GB_SMEM (2*128*132*4 + 64*130*8)

// ---------------- scratch (static device globals; no allocation) ----------------
__device__ int   g_cnt[2][NN];
__device__ int   g_row[2][NN+1];
__device__ int   g_cur[2][NN];
__device__ int   g_csr[2][EE];
__device__ float g_inv[2][NN];
__device__ int   g_bsum[2][128];
__device__ int   g_boff[2][128];
__device__ float g_Y[2][6400000];     // X @ Wl^T   (to be aggregated)
__device__ float g_T[2][6400000];     // X @ Wr^T + b
__device__ float g_hb[4][6400000];    // h0_sc, h0_fc, h1_sc, h1_fc
__device__ float g_pool[GG*256];

// ---------------- f32x2 helpers ----------------
__device__ __forceinline__ void ffma2(uint64_t& c, uint64_t a, uint64_t b) {
    asm("fma.rn.f32x2 %0, %1, %2, %0;" : "+l"(c) : "l"(a), "l"(b));
}
__device__ __forceinline__ uint64_t pack2(float lo, float hi) {
    uint64_t r; asm("mov.b64 %0, {%1, %2};" : "=l"(r) : "f"(lo), "f"(hi)); return r;
}
__device__ __forceinline__ uint64_t dup2(float v) {
    uint64_t r; asm("mov.b64 %0, {%1, %1};" : "=l"(r) : "f"(v)); return r;
}
__device__ __forceinline__ void unpack2(uint64_t p, float& lo, float& hi) {
    asm("mov.b64 {%0, %1}, %2;" : "=f"(lo), "=f"(hi) : "l"(p));
}

// ---------------- zero counters + pooled + row sentinel ----------------
__global__ void zero_kernel() {
    int i = blockIdx.x * blockDim.x + threadIdx.x;
    if (i < 2*NN) ((int*)g_cnt)[i] = 0;
    if (i < GG*256) g_pool[i] = 0.f;
    if (i == 0) { g_row[0][NN] = EE; g_row[1][NN] = EE; }
}

// ---------------- degree histogram (both sets) ----------------
__global__ void count_kernel(const int* __restrict__ dst0, const int* __restrict__ dst1) {
    int e = blockIdx.x * blockDim.x + threadIdx.x;
    if (e < EE)            atomicAdd(&g_cnt[0][dst0[e]], 1);
    else if (e < 2 * EE)   atomicAdd(&g_cnt[1][dst1[e - EE]], 1);
}

// ---------------- phase 1: per-chunk sums ----------------
__global__ void block_reduce_kernel() {     // grid = 2*NB, 256 threads
    int set = blockIdx.x / NB, b = blockIdx.x - set * NB;
    int tid = threadIdx.x;
    int n0 = b * CH + tid;
    int s = 0;
    if (n0 < NN) s += g_cnt[set][n0];
    if (n0 + 256 < NN && tid + 256 < CH) s += g_cnt[set][n0 + 256];
    #pragma unroll
    for (int o = 16; o > 0; o >>= 1) s += __shfl_down_sync(0xffffffffu, s, o);
    __shared__ int ws[8];
    if ((tid & 31) == 0) ws[tid >> 5] = s;
    __syncthreads();
    if (tid == 0) {
        int t = 0;
        #pragma unroll
        for (int w = 0; w < 8; w++) t += ws[w];
        g_bsum[set][b] = t;
    }
}

// ---------------- phase 2: scan chunk sums (1 block) ----------------
__global__ void bsum_scan_kernel() {        // 1 block, 256 threads
    __shared__ int s[2][129];
    int set = threadIdx.x >> 7, i = threadIdx.x & 127;
    int v = (i < NB) ? g_bsum[set][i] : 0;
    s[set][i] = v;
    __syncthreads();
    #pragma unroll
    for (int o = 1; o < 128; o <<= 1) {
        int t = (i >= o) ? s[set][i - o] : 0;
        __syncthreads();
        s[set][i] += t;
        __syncthreads();
    }
    g_boff[set][i] = s[set][i] - v;  // exclusive
}

// ---------------- phase 3: per-chunk scan, write row/cur/inv ----------------
__global__ void chunk_scan_kernel() {       // grid = 2*NB, 512 threads
    int set = blockIdx.x / NB, b = blockIdx.x - set * NB;
    int tid = threadIdx.x, lane = tid & 31, wid = tid >> 5;
    __shared__ int wsum[16];
    int n = b * CH + tid;
    int v = (n < NN) ? g_cnt[set][n] : 0;
    int x = v;
    #pragma unroll
    for (int o = 1; o < 32; o <<= 1) { int y = __shfl_up_sync(0xffffffffu, x, o); if (lane >= o) x += y; }
    if (lane == 31) wsum[wid] = x;
    __syncthreads();
    if (wid == 0 && lane < 16) {
        int w = wsum[lane];
        #pragma unroll
        for (int o = 1; o < 16; o <<= 1) { int y = __shfl_up_sync(0x0000ffffu, w, o); if (lane >= o) w += y; }
        wsum[lane] = w;
    }
    __syncthreads();
    int excl = g_boff[set][b] + (wid ? wsum[wid - 1] : 0) + (x - v);
    if (n < NN) {
        g_row[set][n] = excl;
        g_cur[set][n] = excl;
        g_inv[set][n] = 1.0f / (float)(v > 0 ? v : 1);
    }
}

// ---------------- CSR fill (both sets) ----------------
__global__ void fill_kernel(const int* __restrict__ ei0, const int* __restrict__ ei1) {
    int e = blockIdx.x * blockDim.x + threadIdx.x;
    if (e < EE) {
        int d = ei0[EE + e];
        int p = atomicAdd(&g_cur[0][d], 1);
        g_csr[0][p] = ei0[e];
    } else if (e < 2 * EE) {
        int ee = e - EE;
        int d = ei1[EE + ee];
        int p = atomicAdd(&g_cur[1][d], 1);
        g_csr[1][p] = ei1[ee];
    }
}

// ---------------- wide GEMM: [T|Y] = X @ [Wr|Wl]^T (+bias on T) -------------
// grid = 148 persistent (74 blocks per branch), 256 threads (8 warps).
// Each block iterates 64-row tiles; each warp computes 8 rows x (4 Wr-cols + 4 Wl-cols)/lane.
__global__ __launch_bounds__(256) void gemm_big_kernel(
    const float* __restrict__ X0, const float* __restrict__ Wr0, const float* __restrict__ Wl0,
    const float* __restrict__ b0, float* __restrict__ T0, float* __restrict__ Y0,
    const float* __restrict__ X1, const float* __restrict__ Wr1, const float* __restrict__ Wl1,
    const float* __restrict__ b1, float* __restrict__ T1, float* __restrict__ Y1)
{
    extern __shared__ char smraw[];
    float* sWr = (float*)smraw;                         // [128][132], sWr[k*132+h]=Wr[h][k]
    float* sWl = sWr + 128 * 132;
    uint64_t* sA = (uint64_t*)(smraw + 2*128*132*4);    // [64][130] dup'd row scalars, k-contig

    int br = blockIdx.x & 1;
    int bid = blockIdx.x >> 1;
    int half = gridDim.x >> 1;      // 74
    const float* X  = br ? X1  : X0;
    const float* Wr = br ? Wr1 : Wr0;
    const float* Wl = br ? Wl1 : Wl0;
    const float* bias = br ? b1 : b0;
    float* T = br ? T1 : T0;
    float* Y = br ? Y1 : Y0;

    for (int idx = threadIdx.x; idx < 128 * 128; idx += 256) {
        int h = idx >> 7, k = idx & 127;
        sWr[k * 132 + h] = Wr[idx];
        sWl[k * 132 + h] = Wl[idx];
    }
    int lane = threadIdx.x & 31, wid = threadIdx.x >> 5;

    float4 bv = *reinterpret_cast<const float4*>(bias + lane * 4);
    uint64_t b01 = pack2(bv.x, bv.y), b23 = pack2(bv.z, bv.w);

    for (int base = bid * 64; base < NN; base += half * 64) {
        __syncthreads();
        // stage 8 rows per warp, dup'd; layout sA[r][k] (k contiguous, pitch 130)
        #pragma unroll
        for (int rr = 0; rr < 8; rr++) {
            int r = wid * 8 + rr;
            int row = base + r;
            uint64_t* dst = sA + r * 130 + lane * 4;
            if (row < NN) {
                float4 v = *reinterpret_cast<const float4*>(X + (size_t)row * 128 + lane * 4);
                dst[0] = dup2(v.x); dst[1] = dup2(v.y);
                dst[2] = dup2(v.z); dst[3] = dup2(v.w);
            } else {
                dst[0] = 0; dst[1] = 0; dst[2] = 0; dst[3] = 0;
            }
        }
        __syncthreads();

        uint64_t cT[8][2], cY[8][2];
        #pragma unroll
        for (int r = 0; r < 8; r++) {
            cT[r][0] = b01; cT[r][1] = b23;
            cY[r][0] = 0;   cY[r][1] = 0;
        }
        const uint64_t* aBase = sA + (size_t)(wid * 8) * 130;
        #pragma unroll 4
        for (int k = 0; k < 128; k += 2) {
            const uint64_t* wr0p = reinterpret_cast<const uint64_t*>(sWr + k * 132 + lane * 4);
            const uint64_t* wl0p = reinterpret_cast<const uint64_t*>(sWl + k * 132 + lane * 4);
            const uint64_t* wr1p = reinterpret_cast<const uint64_t*>(sWr + (k + 1) * 132 + lane * 4);
            const uint64_t* wl1p = reinterpret_cast<const uint64_t*>(sWl + (k + 1) * 132 + lane * 4);
            uint64_t wr0a = wr0p[0], wr0b = wr0p[1];
            uint64_t wl0a = wl0p[0], wl0b = wl0p[1];
            uint64_t wr1a = wr1p[0], wr1b = wr1p[1];
            uint64_t wl1a = wl1p[0], wl1b = wl1p[1];
            #pragma unroll
            for (int r = 0; r < 8; r++) {
                // broadcast LDS.128: dup'd scalars for (k, k+1) of row r
                ulonglong2 a2 = *reinterpret_cast<const ulonglong2*>(aBase + r * 130 + k);
                ffma2(cT[r][0], a2.x, wr0a); ffma2(cT[r][1], a2.x, wr0b);
                ffma2(cY[r][0], a2.x, wl0a); ffma2(cY[r][1], a2.x, wl0b);
                ffma2(cT[r][0], a2.y, wr1a); ffma2(cT[r][1], a2.y, wr1b);
                ffma2(cY[r][0], a2.y, wl1a); ffma2(cY[r][1], a2.y, wl1b);
            }
        }
        #pragma unroll
        for (int r = 0; r < 8; r++) {
            int row = base + wid * 8 + r;
            if (row >= NN) break;
            float4 t, y;
            unpack2(cT[r][0], t.x, t.y); unpack2(cT[r][1], t.z, t.w);
            unpack2(cY[r][0], y.x, y.y); unpack2(cY[r][1], y.z, y.w);
            *reinterpret_cast<float4*>(T + (size_t)row * 128 + lane * 4) = t;
            *reinterpret_cast<float4*>(Y + (size_t)row * 128 + lane * 4) = y;
        }
    }
}

// ---------------- aggregation + epilogue: h = relu(T + inv * sum_{j->i} Y[j]) ----------------
__global__ void agg_epi_kernel(
    const float* __restrict__ Y0, const float* __restrict__ T0, float* __restrict__ H0,
    const float* __restrict__ Y1, const float* __restrict__ T1, float* __restrict__ H1)
{
    int gw = (blockIdx.x * blockDim.x + threadIdx.x) >> 5;
    int lane = threadIdx.x & 31;
    if (gw >= 2 * NN) return;
    int set = (gw >= NN) ? 1 : 0;
    int node = gw - set * NN;
    const float* Y = set ? Y1 : Y0;
    const float* T = set ? T1 : T0;
    float* H = set ? H1 : H0;
    int s = g_row[set][node], e = g_row[set][node + 1];
    float ax = 0.f, ay = 0.f, az = 0.f, aw = 0.f;
    for (int b = s; b < e; b += 32) {
        int m = min(32, e - b);
        int sid = (lane < m) ? g_csr[set][b + lane] : 0;
        for (int j = 0; j < m; j++) {
            int sj = __shfl_sync(0xffffffffu, sid, j);
            const float4 v = *reinterpret_cast<const float4*>(Y + (size_t)sj * 128 + lane * 4);
            ax += v.x; ay += v.y; az += v.z; aw += v.w;
        }
    }
    float inv = g_inv[set][node];
    const float4 t = *reinterpret_cast<const float4*>(T + (size_t)node * 128 + lane * 4);
    float4 r;
    r.x = fmaxf(t.x + ax * inv, 0.f);
    r.y = fmaxf(t.y + ay * inv, 0.f);
    r.z = fmaxf(t.z + az * inv, 0.f);
    r.w = fmaxf(t.w + aw * inv, 0.f);
    *reinterpret_cast<float4*>(H + (size_t)node * 128 + lane * 4) = r;
}

// ---------------- global add pool (both branches) ----------------
__global__ void pool_pair_kernel(const float* __restrict__ hsc, const float* __restrict__ hfc,
                                 const int* __restrict__ batch) {
    int idx = blockIdx.x * blockDim.x + threadIdx.x;
    if (idx >= 2 * NN * 32) return;
    int br = (idx >= NN * 32) ? 1 : 0;
    int li = idx - br * NN * 32;
    int node = li >> 5, c4 = li & 31;
    int g = batch[node];
    const float* h = br ? hfc : hsc;
    const float4 v = *reinterpret_cast<const float4*>(h + (size_t)node * 128 + c4 * 4);
    float* d = g_pool + g * 256 + br * 128 + c4 * 4;
    atomicAdd(d + 0, v.x); atomicAdd(d + 1, v.y);
    atomicAdd(d + 2, v.z); atomicAdd(d + 3, v.w);
}

// ---------------- MLP head + log_softmax, one block per graph ----------------
__global__ void head_kernel(
    const float* __restrict__ W1, const float* __restrict__ b1,
    const float* __restrict__ W2, const float* __restrict__ b2,
    const float* __restrict__ W3, const float* __restrict__ b3,
    float* __restrict__ out)
{
    __shared__ float sp[256], sh1[128], sh2[64];
    int g = blockIdx.x, t = threadIdx.x;
    sp[t]       = g_pool[g * 256 + t];
    sp[t + 128] = g_pool[g * 256 + 128 + t];
    __syncthreads();
    float a = b1[t];
    const float* w = W1 + t * 256;
    for (int k = 0; k < 256; k++) a += sp[k] * w[k];
    sh1[t] = fmaxf(a, 0.f);
    __syncthreads();
    if (t < 64) {
        float a2 = b2[t];
        const float* w2 = W2 + t * 128;
        for (int k = 0; k < 128; k++) a2 += sh1[k] * w2[k];
        sh2[t] = fmaxf(a2, 0.f);
    }
    __syncthreads();
    if (t == 0) {
        float l0 = b3[0], l1 = b3[1];
        for (int k = 0; k < 64; k++) { l0 += sh2[k] * W3[k]; l1 += sh2[k] * W3[64 + k]; }
        float m = fmaxf(l0, l1);
        float lse = m + logf(expf(l0 - m) + expf(l1 - m));
        out[g * 2 + 0] = l0 - lse;
        out[g * 2 + 1] = l1 - lse;
    }
}

// ---------------- launch ----------------
extern "C" void kernel_launch(void* const* d_in, const int* in_sizes, int n_in,
                              void* d_out, int out_size) {
    const float* sc_x  = (const float*)d_in[0];
    const float* fc_x  = (const float*)d_in[1];
    const int*   sc_ei = (const int*)d_in[2];
    const int*   fc_ei = (const int*)d_in[3];
    const int*   batch = (const int*)d_in[4];
    const float* scWl1 = (const float*)d_in[5];
    const float* scWr1 = (const float*)d_in[6];
    const float* scb1  = (const float*)d_in[7];
    const float* scWl2 = (const float*)d_in[8];
    const float* scWr2 = (const float*)d_in[9];
    const float* scb2  = (const float*)d_in[10];
    const float* fcWl1 = (const float*)d_in[11];
    const float* fcWr1 = (const float*)d_in[12];
    const float* fcb1  = (const float*)d_in[13];
    const float* fcWl2 = (const float*)d_in[14];
    const float* fcWr2 = (const float*)d_in[15];
    const float* fcb2  = (const float*)d_in[16];
    const float* W1    = (const float*)d_in[17];
    const float* bh1   = (const float*)d_in[18];
    const float* W2    = (const float*)d_in[19];
    const float* bh2   = (const float*)d_in[20];
    const float* W3    = (const float*)d_in[21];
    const float* bh3   = (const float*)d_in[22];
    float* out = (float*)d_out;

    cudaFuncSetAttribute(gemm_big_kernel, cudaFuncAttributeMaxDynamicSharedMemorySize, GB_SMEM);

    float *yb, *tb, *hb;
    cudaGetSymbolAddress((void**)&yb, g_Y);
    cudaGetSymbolAddress((void**)&tb, g_T);
    cudaGetSymbolAddress((void**)&hb, g_hb);
    float* y0 = yb;
    float* y1 = yb + (size_t)6400000;
    float* t0 = tb;
    float* t1 = tb + (size_t)6400000;
    float* h0sc = hb;
    float* h0fc = hb + (size_t)6400000;
    float* h1sc = hb + (size_t)2 * 6400000;
    float* h1fc = hb + (size_t)3 * 6400000;

    int eb2 = (2 * EE + 255) / 256;
    int ab2 = (2 * NN * 32 + 255) / 256;

    zero_kernel<<<(2*NN + 255) / 256, 256>>>();                  // 1
    count_kernel<<<eb2, 256>>>(sc_ei + EE, fc_ei + EE);          // 2
    block_reduce_kernel<<<2 * NB, 256>>>();                      // 3
    // launch #4 -> profiled: layer-1 wide GEMM (no CSR dependency)
    gemm_big_kernel<<<148, 256, GB_SMEM>>>(                      // 4
        sc_x, scWr1, scWl1, scb1, t0, y0,
        fc_x, fcWr1, fcWl1, fcb1, t1, y1);
    bsum_scan_kernel<<<1, 256>>>();                              // 5
    chunk_scan_kernel<<<2 * NB, CH>>>();                         // 6
    fill_kernel<<<eb2, 256>>>(sc_ei, fc_ei);                     // 7

    // layer 1 aggregation + epilogue
    agg_epi_kernel<<<ab2, 256>>>(y0, t0, h0sc, y1, t1, h0fc);    // 8

    // layer 2
    gemm_big_kernel<<<148, 256, GB_SMEM>>>(                      // 9
        h0sc, scWr2, scWl2, scb2, t0, y0,
        h0fc, fcWr2, fcWl2, fcb2, t1, y1);
    agg_epi_kernel<<<ab2, 256>>>(y0, t0, h1sc, y1, t1, h1fc);    // 10

    pool_pair_kernel<<<ab2, 256>>>(h1sc, h1fc, batch);           // 11
    head_kernel<<<GG, 128>>>(W1, bh1, W2, bh2, W3, bh3, out);    // 12
}

// round 8
// speedup vs baseline: 1.5254x; 1.2495x over previous
#include <cuda_runtime.h>
#include <cuda_bf16.h>
#include <math.h>
#include <stdint.h>

#define NN 50000
#define EE 800000
#define GG 64
#define CH 512
#define NB ((NN + CH - 1) / CH)       // 98 chunks
#define NTILES ((NN + 127) / 128)     // 391

// smem: bias 512B | A [128][264] bf16 (hi|lo, pitch 528B) | B [128][392] bf16 (Whi|Whi|Wlo, pitch 784B)
#define SM_BIAS 0
#define SM_A    512
#define SM_B    (512 + 128 * 528)
#define MM_SMEM (512 + 128 * 528 + 128 * 784)

// ---------------- scratch (static device globals; no allocation) ----------------
__device__ int   g_cnt[2][NN];
__device__ int   g_row[2][NN+1];
__device__ int   g_cur[2][NN];
__device__ int   g_csr[2][EE];
__device__ float g_inv[2][NN];
__device__ int   g_bsum[2][128];
__device__ int   g_boff[2][128];
__device__ float g_Y[2][6400000];     // X @ Wl^T   (to be aggregated)
__device__ float g_T[2][6400000];     // X @ Wr^T + b
__device__ float g_hb[4][6400000];    // h0_sc, h0_fc, h1_sc, h1_fc
__device__ float g_pool[GG*256];

// ---------------- helpers ----------------
__device__ __forceinline__ uint32_t smem_u32(const void* p) {
    uint32_t a;
    asm("{ .reg .u64 t; cvta.to.shared.u64 t, %1; cvt.u32.u64 %0, t; }" : "=r"(a) : "l"(p));
    return a;
}
__device__ __forceinline__ uint2 hilo_pack(float4 v, uint2& lo) {
    __nv_bfloat16 h0 = __float2bfloat16_rn(v.x);
    __nv_bfloat16 h1 = __float2bfloat16_rn(v.y);
    __nv_bfloat16 h2 = __float2bfloat16_rn(v.z);
    __nv_bfloat16 h3 = __float2bfloat16_rn(v.w);
    __nv_bfloat16 l0 = __float2bfloat16_rn(v.x - __bfloat162float(h0));
    __nv_bfloat16 l1 = __float2bfloat16_rn(v.y - __bfloat162float(h1));
    __nv_bfloat16 l2 = __float2bfloat16_rn(v.z - __bfloat162float(h2));
    __nv_bfloat16 l3 = __float2bfloat16_rn(v.w - __bfloat162float(h3));
    uint2 hi;
    hi.x = (uint32_t)__bfloat16_as_ushort(h0) | ((uint32_t)__bfloat16_as_ushort(h1) << 16);
    hi.y = (uint32_t)__bfloat16_as_ushort(h2) | ((uint32_t)__bfloat16_as_ushort(h3) << 16);
    lo.x = (uint32_t)__bfloat16_as_ushort(l0) | ((uint32_t)__bfloat16_as_ushort(l1) << 16);
    lo.y = (uint32_t)__bfloat16_as_ushort(l2) | ((uint32_t)__bfloat16_as_ushort(l3) << 16);
    return hi;
}

// ---------------- zero counters + pooled + row sentinel ----------------
__global__ void zero_kernel() {
    int i = blockIdx.x * blockDim.x + threadIdx.x;
    if (i < 2*NN) ((int*)g_cnt)[i] = 0;
    if (i < GG*256) g_pool[i] = 0.f;
    if (i == 0) { g_row[0][NN] = EE; g_row[1][NN] = EE; }
}

// ---------------- degree histogram (both sets) ----------------
__global__ void count_kernel(const int* __restrict__ dst0, const int* __restrict__ dst1) {
    int e = blockIdx.x * blockDim.x + threadIdx.x;
    if (e < EE)            atomicAdd(&g_cnt[0][dst0[e]], 1);
    else if (e < 2 * EE)   atomicAdd(&g_cnt[1][dst1[e - EE]], 1);
}

// ---------------- phase 1: per-chunk sums ----------------
__global__ void block_reduce_kernel() {
    int set = blockIdx.x / NB, b = blockIdx.x - set * NB;
    int tid = threadIdx.x;
    int n0 = b * CH + tid;
    int s = 0;
    if (n0 < NN) s += g_cnt[set][n0];
    if (n0 + 256 < NN && tid + 256 < CH) s += g_cnt[set][n0 + 256];
    #pragma unroll
    for (int o = 16; o > 0; o >>= 1) s += __shfl_down_sync(0xffffffffu, s, o);
    __shared__ int ws[8];
    if ((tid & 31) == 0) ws[tid >> 5] = s;
    __syncthreads();
    if (tid == 0) {
        int t = 0;
        #pragma unroll
        for (int w = 0; w < 8; w++) t += ws[w];
        g_bsum[set][b] = t;
    }
}

// ---------------- phase 2: scan chunk sums (1 block) ----------------
__global__ void bsum_scan_kernel() {
    __shared__ int s[2][129];
    int set = threadIdx.x >> 7, i = threadIdx.x & 127;
    int v = (i < NB) ? g_bsum[set][i] : 0;
    s[set][i] = v;
    __syncthreads();
    #pragma unroll
    for (int o = 1; o < 128; o <<= 1) {
        int t = (i >= o) ? s[set][i - o] : 0;
        __syncthreads();
        s[set][i] += t;
        __syncthreads();
    }
    g_boff[set][i] = s[set][i] - v;
}

// ---------------- phase 3: per-chunk scan ----------------
__global__ void chunk_scan_kernel() {
    int set = blockIdx.x / NB, b = blockIdx.x - set * NB;
    int tid = threadIdx.x, lane = tid & 31, wid = tid >> 5;
    __shared__ int wsum[16];
    int n = b * CH + tid;
    int v = (n < NN) ? g_cnt[set][n] : 0;
    int x = v;
    #pragma unroll
    for (int o = 1; o < 32; o <<= 1) { int y = __shfl_up_sync(0xffffffffu, x, o); if (lane >= o) x += y; }
    if (lane == 31) wsum[wid] = x;
    __syncthreads();
    if (wid == 0 && lane < 16) {
        int w = wsum[lane];
        #pragma unroll
        for (int o = 1; o < 16; o <<= 1) { int y = __shfl_up_sync(0x0000ffffu, w, o); if (lane >= o) w += y; }
        wsum[lane] = w;
    }
    __syncthreads();
    int excl = g_boff[set][b] + (wid ? wsum[wid - 1] : 0) + (x - v);
    if (n < NN) {
        g_row[set][n] = excl;
        g_cur[set][n] = excl;
        g_inv[set][n] = 1.0f / (float)(v > 0 ? v : 1);
    }
}

// ---------------- CSR fill (both sets) ----------------
__global__ void fill_kernel(const int* __restrict__ ei0, const int* __restrict__ ei1) {
    int e = blockIdx.x * blockDim.x + threadIdx.x;
    if (e < EE) {
        int d = ei0[EE + e];
        int p = atomicAdd(&g_cur[0][d], 1);
        g_csr[0][p] = ei0[e];
    } else if (e < 2 * EE) {
        int ee = e - EE;
        int d = ei1[EE + ee];
        int p = atomicAdd(&g_cur[1][d], 1);
        g_csr[1][p] = ei1[ee];
    }
}

// ---------------- HMMA bf16 GEMM with 3-term fp32 compensation ----------------
// grid = 148 CTAs (bit0=branch, bit1=N-half Wr/Wl, rest=cta-id in 0..36), 256 threads.
// Per tile (128 rows): D = Xhi@Whi^T + Xlo@Whi^T + Xhi@Wlo^T  (K=384 unified loop).
__global__ __launch_bounds__(256) void gemm_hmma_kernel(
    const float* __restrict__ X0, const float* __restrict__ Wr0, const float* __restrict__ Wl0,
    const float* __restrict__ b0, float* __restrict__ T0, float* __restrict__ Y0,
    const float* __restrict__ X1, const float* __restrict__ Wr1, const float* __restrict__ Wl1,
    const float* __restrict__ b1, float* __restrict__ T1, float* __restrict__ Y1)
{
    extern __shared__ char sm[];
    uint32_t smb = smem_u32(sm);
    float* sBias = (float*)(sm + SM_BIAS);
    int tid = threadIdx.x, wid = tid >> 5, lane = tid & 31;

    int br  = blockIdx.x & 1;
    int nh  = (blockIdx.x >> 1) & 1;
    int cid = blockIdx.x >> 2;          // 0..36

    const float* X = br ? X1 : X0;
    const float* W = nh ? (br ? Wl1 : Wl0) : (br ? Wr1 : Wr0);
    const float* bias = br ? b1 : b0;
    float* OUT = nh ? (br ? Y1 : Y0) : (br ? T1 : T0);

    // ---- stage W once: B[n][0:128]=Whi, [128:256]=Whi, [256:384]=Wlo ----
    if (tid < 128) sBias[tid] = nh ? 0.f : bias[tid];
    for (int i = tid; i < 128 * 32; i += 256) {
        int n = i >> 5, kq = (i & 31) * 4;
        float4 v = *reinterpret_cast<const float4*>(W + (size_t)n * 128 + kq);
        uint2 lo, hi = hilo_pack(v, lo);
        char* rowp = sm + SM_B + n * 784;
        *reinterpret_cast<uint2*>(rowp + kq * 2)         = hi;
        *reinterpret_cast<uint2*>(rowp + (kq + 128) * 2) = hi;
        *reinterpret_cast<uint2*>(rowp + (kq + 256) * 2) = lo;
    }

    // per-lane ldmatrix base addresses
    int mstrip = wid * 16;
    uint32_t aBase = smb + SM_A + (mstrip + (lane & 15)) * 528 + ((lane >> 4) << 4);
    uint32_t bBase = smb + SM_B + ((lane & 7) + ((lane >> 4) << 3)) * 784 + (((lane >> 3) & 1) << 4);

    for (int tile = cid; tile < NTILES; tile += 37) {
        int row0 = tile * 128;
        __syncthreads();
        // ---- stage A tile: A[m][0:128]=Xhi, [128:256]=Xlo ----
        for (int i = tid; i < 128 * 32; i += 256) {
            int m = i >> 5, kq = (i & 31) * 4;
            int grow = row0 + m;
            float4 v = (grow < NN) ? *reinterpret_cast<const float4*>(X + (size_t)grow * 128 + kq)
                                   : make_float4(0.f, 0.f, 0.f, 0.f);
            uint2 lo, hi = hilo_pack(v, lo);
            char* rowp = sm + SM_A + m * 528;
            *reinterpret_cast<uint2*>(rowp + kq * 2)         = hi;
            *reinterpret_cast<uint2*>(rowp + (kq + 128) * 2) = lo;
        }
        __syncthreads();

        float c[16][4];
        #pragma unroll
        for (int nt = 0; nt < 16; nt++)
            { c[nt][0] = 0.f; c[nt][1] = 0.f; c[nt][2] = 0.f; c[nt][3] = 0.f; }

        for (int ks = 0; ks < 24; ks++) {
            int kk = ks * 16;
            int akk = (kk < 256) ? kk : (kk - 256);   // third segment re-reads Xhi
            uint32_t a0, a1, a2, a3;
            asm volatile("ldmatrix.sync.aligned.m8n8.x4.shared.b16 {%0,%1,%2,%3}, [%4];"
                         : "=r"(a0), "=r"(a1), "=r"(a2), "=r"(a3)
                         : "r"(aBase + akk * 2) : "memory");
            #pragma unroll
            for (int np = 0; np < 8; np++) {
                uint32_t b0r, b1r, b2r, b3r;
                asm volatile("ldmatrix.sync.aligned.m8n8.x4.shared.b16 {%0,%1,%2,%3}, [%4];"
                             : "=r"(b0r), "=r"(b1r), "=r"(b2r), "=r"(b3r)
                             : "r"(bBase + np * (16 * 784) + kk * 2) : "memory");
                asm volatile("mma.sync.aligned.m16n8k16.row.col.f32.bf16.bf16.f32 "
                             "{%0,%1,%2,%3}, {%4,%5,%6,%7}, {%8,%9}, {%0,%1,%2,%3};"
                             : "+f"(c[2*np][0]), "+f"(c[2*np][1]), "+f"(c[2*np][2]), "+f"(c[2*np][3])
                             : "r"(a0), "r"(a1), "r"(a2), "r"(a3), "r"(b0r), "r"(b1r));
                asm volatile("mma.sync.aligned.m16n8k16.row.col.f32.bf16.bf16.f32 "
                             "{%0,%1,%2,%3}, {%4,%5,%6,%7}, {%8,%9}, {%0,%1,%2,%3};"
                             : "+f"(c[2*np+1][0]), "+f"(c[2*np+1][1]), "+f"(c[2*np+1][2]), "+f"(c[2*np+1][3])
                             : "r"(a0), "r"(a1), "r"(a2), "r"(a3), "r"(b2r), "r"(b3r));
            }
        }

        // ---- epilogue ----
        int r0 = row0 + mstrip + (lane >> 2);
        int r1 = r0 + 8;
        int cbase = (lane & 3) * 2;
        #pragma unroll
        for (int nt = 0; nt < 16; nt++) {
            int col = nt * 8 + cbase;
            float bb0 = sBias[col], bb1 = sBias[col + 1];
            if (r0 < NN) {
                float2 o; o.x = c[nt][0] + bb0; o.y = c[nt][1] + bb1;
                *reinterpret_cast<float2*>(OUT + (size_t)r0 * 128 + col) = o;
            }
            if (r1 < NN) {
                float2 o; o.x = c[nt][2] + bb0; o.y = c[nt][3] + bb1;
                *reinterpret_cast<float2*>(OUT + (size_t)r1 * 128 + col) = o;
            }
        }
    }
}

// ---------------- aggregation + epilogue: h = relu(T + inv * sum_{j->i} Y[j]) ----------------
__global__ void agg_epi_kernel(
    const float* __restrict__ Y0, const float* __restrict__ T0, float* __restrict__ H0,
    const float* __restrict__ Y1, const float* __restrict__ T1, float* __restrict__ H1)
{
    int gw = (blockIdx.x * blockDim.x + threadIdx.x) >> 5;
    int lane = threadIdx.x & 31;
    if (gw >= 2 * NN) return;
    int set = (gw >= NN) ? 1 : 0;
    int node = gw - set * NN;
    const float* Y = set ? Y1 : Y0;
    const float* T = set ? T1 : T0;
    float* H = set ? H1 : H0;
    int s = g_row[set][node], e = g_row[set][node + 1];
    float ax = 0.f, ay = 0.f, az = 0.f, aw = 0.f;
    for (int b = s; b < e; b += 32) {
        int m = min(32, e - b);
        int sid = (lane < m) ? g_csr[set][b + lane] : 0;
        for (int j = 0; j < m; j++) {
            int sj = __shfl_sync(0xffffffffu, sid, j);
            const float4 v = *reinterpret_cast<const float4*>(Y + (size_t)sj * 128 + lane * 4);
            ax += v.x; ay += v.y; az += v.z; aw += v.w;
        }
    }
    float inv = g_inv[set][node];
    const float4 t = *reinterpret_cast<const float4*>(T + (size_t)node * 128 + lane * 4);
    float4 r;
    r.x = fmaxf(t.x + ax * inv, 0.f);
    r.y = fmaxf(t.y + ay * inv, 0.f);
    r.z = fmaxf(t.z + az * inv, 0.f);
    r.w = fmaxf(t.w + aw * inv, 0.f);
    *reinterpret_cast<float4*>(H + (size_t)node * 128 + lane * 4) = r;
}

// ---------------- global add pool (both branches) ----------------
__global__ void pool_pair_kernel(const float* __restrict__ hsc, const float* __restrict__ hfc,
                                 const int* __restrict__ batch) {
    int idx = blockIdx.x * blockDim.x + threadIdx.x;
    if (idx >= 2 * NN * 32) return;
    int br = (idx >= NN * 32) ? 1 : 0;
    int li = idx - br * NN * 32;
    int node = li >> 5, c4 = li & 31;
    int g = batch[node];
    const float* h = br ? hfc : hsc;
    const float4 v = *reinterpret_cast<const float4*>(h + (size_t)node * 128 + c4 * 4);
    float* d = g_pool + g * 256 + br * 128 + c4 * 4;
    atomicAdd(d + 0, v.x); atomicAdd(d + 1, v.y);
    atomicAdd(d + 2, v.z); atomicAdd(d + 3, v.w);
}

// ---------------- MLP head + log_softmax, one block per graph ----------------
__global__ void head_kernel(
    const float* __restrict__ W1, const float* __restrict__ b1,
    const float* __restrict__ W2, const float* __restrict__ b2,
    const float* __restrict__ W3, const float* __restrict__ b3,
    float* __restrict__ out)
{
    __shared__ float sp[256], sh1[128], sh2[64];
    int g = blockIdx.x, t = threadIdx.x;
    sp[t]       = g_pool[g * 256 + t];
    sp[t + 128] = g_pool[g * 256 + 128 + t];
    __syncthreads();
    float a = b1[t];
    const float* w = W1 + t * 256;
    for (int k = 0; k < 256; k++) a += sp[k] * w[k];
    sh1[t] = fmaxf(a, 0.f);
    __syncthreads();
    if (t < 64) {
        float a2 = b2[t];
        const float* w2 = W2 + t * 128;
        for (int k = 0; k < 128; k++) a2 += sh1[k] * w2[k];
        sh2[t] = fmaxf(a2, 0.f);
    }
    __syncthreads();
    if (t == 0) {
        float l0 = b3[0], l1 = b3[1];
        for (int k = 0; k < 64; k++) { l0 += sh2[k] * W3[k]; l1 += sh2[k] * W3[64 + k]; }
        float m = fmaxf(l0, l1);
        float lse = m + logf(expf(l0 - m) + expf(l1 - m));
        out[g * 2 + 0] = l0 - lse;
        out[g * 2 + 1] = l1 - lse;
    }
}

// ---------------- launch ----------------
extern "C" void kernel_launch(void* const* d_in, const int* in_sizes, int n_in,
                              void* d_out, int out_size) {
    const float* sc_x  = (const float*)d_in[0];
    const float* fc_x  = (const float*)d_in[1];
    const int*   sc_ei = (const int*)d_in[2];
    const int*   fc_ei = (const int*)d_in[3];
    const int*   batch = (const int*)d_in[4];
    const float* scWl1 = (const float*)d_in[5];
    const float* scWr1 = (const float*)d_in[6];
    const float* scb1  = (const float*)d_in[7];
    const float* scWl2 = (const float*)d_in[8];
    const float* scWr2 = (const float*)d_in[9];
    const float* scb2  = (const float*)d_in[10];
    const float* fcWl1 = (const float*)d_in[11];
    const float* fcWr1 = (const float*)d_in[12];
    const float* fcb1  = (const float*)d_in[13];
    const float* fcWl2 = (const float*)d_in[14];
    const float* fcWr2 = (const float*)d_in[15];
    const float* fcb2  = (const float*)d_in[16];
    const float* W1    = (const float*)d_in[17];
    const float* bh1   = (const float*)d_in[18];
    const float* W2    = (const float*)d_in[19];
    const float* bh2   = (const float*)d_in[20];
    const float* W3    = (const float*)d_in[21];
    const float* bh3   = (const float*)d_in[22];
    float* out = (float*)d_out;

    cudaFuncSetAttribute(gemm_hmma_kernel, cudaFuncAttributeMaxDynamicSharedMemorySize, MM_SMEM);

    float *yb, *tb, *hb;
    cudaGetSymbolAddress((void**)&yb, g_Y);
    cudaGetSymbolAddress((void**)&tb, g_T);
    cudaGetSymbolAddress((void**)&hb, g_hb);
    float* y0 = yb;
    float* y1 = yb + (size_t)6400000;
    float* t0 = tb;
    float* t1 = tb + (size_t)6400000;
    float* h0sc = hb;
    float* h0fc = hb + (size_t)6400000;
    float* h1sc = hb + (size_t)2 * 6400000;
    float* h1fc = hb + (size_t)3 * 6400000;

    int eb2 = (2 * EE + 255) / 256;
    int ab2 = (2 * NN * 32 + 255) / 256;

    zero_kernel<<<(2*NN + 255) / 256, 256>>>();                  // 1
    count_kernel<<<eb2, 256>>>(sc_ei + EE, fc_ei + EE);          // 2
    block_reduce_kernel<<<2 * NB, 256>>>();                      // 3
    // launch #4 -> profiled: layer-1 HMMA GEMM (no CSR dependency)
    gemm_hmma_kernel<<<148, 256, MM_SMEM>>>(                     // 4
        sc_x, scWr1, scWl1, scb1, t0, y0,
        fc_x, fcWr1, fcWl1, fcb1, t1, y1);
    bsum_scan_kernel<<<1, 256>>>();                              // 5
    chunk_scan_kernel<<<2 * NB, CH>>>();                         // 6
    fill_kernel<<<eb2, 256>>>(sc_ei, fc_ei);                     // 7

    agg_epi_kernel<<<ab2, 256>>>(y0, t0, h0sc, y1, t1, h0fc);    // 8

    gemm_hmma_kernel<<<148, 256, MM_SMEM>>>(                     // 9
        h0sc, scWr2, scWl2, scb2, t0, y0,
        h0fc, fcWr2, fcWl2, fcb2, t1, y1);
    agg_epi_kernel<<<ab2, 256>>>(y0, t0, h1sc, y1, t1, h1fc);    // 10

    pool_pair_kernel<<<ab2, 256>>>(h1sc, h1fc, batch);           // 11
    head_kernel<<<GG, 128>>>(W1, bh1, W2, bh2, W3, bh3, out);    // 12
}